// round 14
// baseline (speedup 1.0000x reference)
#include <cuda_runtime.h>
#include <cstdint>

#define BB 64
#define NN 1024
#define IC 16
#define HC 64
#define OC 32

// Scratch (allocation-free rule: device globals)
__device__ float g_h  [BB * NN * HC];   // linear1 output (tf32-rounded)
__device__ float g_h2 [BB * NN * HC];   // propagate1 output
__device__ float g_o1 [BB * NN * OC];   // linear2 output (tf32-rounded)
__device__ float g_invdeg[BB * NN];     // 1/(deg+1), produced by propagate1

__device__ __forceinline__ float to_tf32(float x) {
    uint32_t u;
    asm("cvt.rna.tf32.f32 %0, %1;" : "=r"(u) : "f"(x));
    return __uint_as_float(u);
}

__device__ __forceinline__ void mma8(float c[4], const uint32_t a[4], const uint32_t b[2]) {
    asm volatile(
        "mma.sync.aligned.m16n8k8.row.col.f32.tf32.tf32.f32 "
        "{%0,%1,%2,%3}, {%4,%5,%6,%7}, {%8,%9}, {%0,%1,%2,%3};\n"
        : "+f"(c[0]), "+f"(c[1]), "+f"(c[2]), "+f"(c[3])
        : "r"(a[0]), "r"(a[1]), "r"(a[2]), "r"(a[3]), "r"(b[0]), "r"(b[1]));
}

__device__ __forceinline__ void ldgsts16(uint32_t dst, const float* src) {
    asm volatile("cp.async.cg.shared.global [%0], [%1], 16;\n" :: "r"(dst), "l"(src));
}

// ---------------------------------------------------------------------------
// Linear 1: h = tf32_round(x @ W1^T + b1)   ([B,N,16] -> [B,N,64])
// ---------------------------------------------------------------------------
__global__ void __launch_bounds__(256) k_lin1(const float* __restrict__ x,
                                              const float* __restrict__ W1,
                                              const float* __restrict__ b1) {
    __shared__ float xs[64][17];
    __shared__ float ws[64][16];
    __shared__ float bs[64];

    int tile = blockIdx.x;
    int b = tile >> 4;
    int n0 = (tile & 15) * 64;
    int t = threadIdx.x;

    const float* xp = x + ((size_t)b * NN + n0) * IC;
    for (int i = t; i < 64 * 16; i += 256) xs[i >> 4][i & 15] = xp[i];
    for (int i = t; i < 64 * 16; i += 256) ws[i >> 4][i & 15] = W1[i];
    if (t < 64) bs[t] = b1[t];
    __syncthreads();

    int row = t & 63;
    int c0 = (t >> 6) * 16;
    float acc[16];
#pragma unroll
    for (int j = 0; j < 16; j++) acc[j] = bs[c0 + j];
#pragma unroll
    for (int c = 0; c < 16; c++) {
        float xv = xs[row][c];
#pragma unroll
        for (int j = 0; j < 16; j++) acc[j] += xv * ws[c0 + j][c];
    }
    float* hp = g_h + ((size_t)b * NN + n0 + row) * HC + c0;
#pragma unroll
    for (int j = 0; j < 16; j++) hp[j] = to_tf32(acc[j]);   // unbiased tf32 at source
}

// ---------------------------------------------------------------------------
// Linear 2: o1 = tf32_round(h2 @ W2^T + b2)   ([B,N,64] -> [B,N,32])
// ---------------------------------------------------------------------------
__global__ void __launch_bounds__(256) k_lin2(const float* __restrict__ W2,
                                              const float* __restrict__ b2) {
    __shared__ float hs[64][65];
    __shared__ float ws[32][64];
    __shared__ float bs[32];

    int tile = blockIdx.x;
    int b = tile >> 4;
    int n0 = (tile & 15) * 64;
    int t = threadIdx.x;

    const float4* hp4 = (const float4*)(g_h2 + ((size_t)b * NN + n0) * HC);
    for (int j = t; j < 64 * 16; j += 256) {
        float4 v = hp4[j];
        int r = j >> 4, c = (j & 15) * 4;
        hs[r][c] = v.x; hs[r][c + 1] = v.y; hs[r][c + 2] = v.z; hs[r][c + 3] = v.w;
    }
    const float4* wp4 = (const float4*)W2;
    for (int j = t; j < 32 * 16; j += 256) {
        float4 v = wp4[j];
        int r = j >> 4, c = (j & 15) * 4;
        ws[r][c] = v.x; ws[r][c + 1] = v.y; ws[r][c + 2] = v.z; ws[r][c + 3] = v.w;
    }
    if (t < 32) bs[t] = b2[t];
    __syncthreads();

    int row = t & 63;
    int c0 = (t >> 6) * 8;
    float acc[8];
#pragma unroll
    for (int j = 0; j < 8; j++) acc[j] = bs[c0 + j];
#pragma unroll
    for (int c = 0; c < 64; c++) {
        float xv = hs[row][c];
#pragma unroll
        for (int j = 0; j < 8; j++) acc[j] += xv * ws[c0 + j][c];
    }
    float* op = g_o1 + ((size_t)b * NN + n0 + row) * OC + c0;
#pragma unroll
    for (int j = 0; j < 8; j++) op[j] = to_tf32(acc[j]);    // unbiased tf32 at source
}

// ---------------------------------------------------------------------------
// Propagate: Out = relu((A_raw @ Hin + Hin_self) * inv_deg)
//  3-stage cp.async pipeline, conservative 2-barrier skeleton:
//    commit group(it+2); wait_group 2 -> stage it%3 resident; sync; compute; sync.
//  Uniform layout: 8 M-warps x 16 rows; each warp does all NT n-tiles.
//  FIRST  (prop1): NT=9 (cols 0..63 + deg column at col 64 in the pad),
//                  writes g_h2 + g_invdeg (each warp owns its rows' degree).
//  !FIRST (prop2): NT=4 (cols 0..31), reads g_invdeg, writes d_out.
// ---------------------------------------------------------------------------
template <int C, int HSTR, bool FIRST>
__global__ void __launch_bounds__(256) k_prop(const float* __restrict__ G,
                                              float* __restrict__ OutParam) {
    constexpr int BM = 128, BK = 32, S = 3;
    constexpr int GS_STG = BM * BK;               // 4096 floats/stage
    constexpr int HS_STG = BK * HSTR;
    constexpr int NT = FIRST ? 9 : 4;             // n-tiles (incl. deg when FIRST)
    constexpr int NTO = C / 8;                    // output n-tiles
    constexpr int NITER = NN / BK;                // 32
    constexpr int HCH = BK * (C / 4);             // H 16B chunks per tile

    extern __shared__ float smem[];
    float* Gs = smem;                              // [S][GS_STG]
    float* Hs = smem + S * GS_STG;                 // [S][HS_STG]

    const int blk = blockIdx.x;
    const int b = blk >> 3;
    const int m0 = (blk & 7) * BM;

    const float* Gp = G + ((size_t)b * NN + m0) * NN;
    const float* Hin = FIRST ? g_h : g_o1;
    const float* Hp = Hin + (size_t)b * NN * C;
    float* Out = FIRST ? g_h2 : OutParam;

    const int t = threadIdx.x;
    const int warp = t >> 5;
    const int lane = t & 31;
    const int g4 = lane >> 2;
    const int tg = lane & 3;

    const uint32_t gs_u = (uint32_t)__cvta_generic_to_shared(Gs);
    const uint32_t hs_u = (uint32_t)__cvta_generic_to_shared(Hs);

    // constant pad init (ones/deg column lives at col C when FIRST);
    // cp.async never touches the pad; first read is after the loop's barrier.
    for (int i = t; i < S * BK * (HSTR - C); i += 256) {
        int s = i / (BK * (HSTR - C));
        int r = (i / (HSTR - C)) % BK;
        int c = i % (HSTR - C);
        Hs[s * HS_STG + r * HSTR + C + c] = (FIRST && c == 0) ? 1.0f : 0.0f;
    }

    auto load_tiles = [&](int stg, int it) {
        const int k0 = it * BK;
#pragma unroll
        for (int i = 0; i < 4; ++i) {             // G: 1024 chunks / 256 thr
            int idx = t + i * 256;
            int r = idx >> 3, c = idx & 7;
            ldgsts16(gs_u + (uint32_t)(stg * GS_STG + r * BK + ((c ^ (r & 7)) << 2)) * 4u,
                     Gp + (size_t)r * NN + k0 + c * 4);
        }
#pragma unroll
        for (int i = 0; i < HCH / 256; ++i) {     // H
            int idx = t + i * 256;
            int r = idx / (C / 4), c = idx % (C / 4);
            ldgsts16(hs_u + (uint32_t)(stg * HS_STG + r * HSTR + c * 4) * 4u,
                     Hp + (size_t)(k0 + r) * C + c * 4);
        }
    };

    float acc[NT][4];
#pragma unroll
    for (int nt = 0; nt < NT; nt++)
#pragma unroll
        for (int j = 0; j < 4; j++) acc[nt][j] = 0.f;

    // ---- prologue: tiles 0,1 into stages 0,1 ----
    load_tiles(0, 0);
    asm volatile("cp.async.commit_group;\n");
    load_tiles(1, 1);
    asm volatile("cp.async.commit_group;\n");

    for (int it = 0; it < NITER; ++it) {
        if (it + 2 < NITER) load_tiles((it + 2) % S, it + 2);
        asm volatile("cp.async.commit_group;\n");
        // pending <= 2 (groups it+1, it+2)  =>  group `it` retired
        asm volatile("cp.async.wait_group 2;\n");
        __syncthreads();

        const float* Gb = Gs + (it % S) * GS_STG;
        const float* Hb = Hs + (it % S) * HS_STG;
#pragma unroll
        for (int ks = 0; ks < BK / 8; ++ks) {
            uint32_t afr[4];
            {
                int r0 = warp * 16 + g4;
                int base  = r0 * BK + (((2 * ks)     ^ (r0 & 7)) << 2) + tg;
                int base2 = r0 * BK + (((2 * ks + 1) ^ (r0 & 7)) << 2) + tg;
                afr[0] = __float_as_uint(Gb[base]);
                afr[1] = __float_as_uint(Gb[base + 8 * BK]);
                afr[2] = __float_as_uint(Gb[base2]);
                afr[3] = __float_as_uint(Gb[base2 + 8 * BK]);
            }
#pragma unroll
            for (int nt = 0; nt < NT; ++nt) {
                int n = nt * 8 + g4;
                uint32_t bfr[2];
                bfr[0] = __float_as_uint(Hb[(ks * 8 + tg) * HSTR + n]);
                bfr[1] = __float_as_uint(Hb[(ks * 8 + tg + 4) * HSTR + n]);
                mma8(acc[nt], afr, bfr);
            }
        }
        // loads at iter it+1 target stage (it+3)%S == it%S; this barrier orders
        // all reads of stage it%S before those overwrites.
        __syncthreads();
    }

    // --- epilogue: self-loop add, degree scale, relu ---
    int rl = warp * 16 + g4;
    int row0 = m0 + rl;
    int row1 = row0 + 8;
    float inv0, inv1;
    if (FIRST) {
        // degree = col C (tile 8, intra col 0) -> acc[8][0]/acc[8][2] of tg==0 lanes
        float d0 = __shfl_sync(0xffffffffu, acc[NT - 1][0], lane & ~3);
        float d1 = __shfl_sync(0xffffffffu, acc[NT - 1][2], lane & ~3);
        inv0 = 1.0f / (d0 + 1.0f);
        inv1 = 1.0f / (d1 + 1.0f);
        if (tg == 0) {
            g_invdeg[(size_t)b * NN + row0] = inv0;
            g_invdeg[(size_t)b * NN + row1] = inv1;
        }
    } else {
        inv0 = g_invdeg[(size_t)b * NN + row0];
        inv1 = g_invdeg[(size_t)b * NN + row1];
    }
#pragma unroll
    for (int nt = 0; nt < NTO; ++nt) {
        int col = nt * 8 + 2 * tg;
        float2 s0 = *(const float2*)(Hin + ((size_t)b * NN + row0) * C + col);
        float2 s1 = *(const float2*)(Hin + ((size_t)b * NN + row1) * C + col);
        float2 r0, r1;
        r0.x = fmaxf((acc[nt][0] + s0.x) * inv0, 0.f);
        r0.y = fmaxf((acc[nt][1] + s0.y) * inv0, 0.f);
        r1.x = fmaxf((acc[nt][2] + s1.x) * inv1, 0.f);
        r1.y = fmaxf((acc[nt][3] + s1.y) * inv1, 0.f);
        *(float2*)(Out + ((size_t)b * NN + row0) * C + col) = r0;
        *(float2*)(Out + ((size_t)b * NN + row1) * C + col) = r1;
    }
}

extern "C" void kernel_launch(void* const* d_in, const int* in_sizes, int n_in,
                              void* d_out, int out_size) {
    const float* x     = (const float*)d_in[0];
    const float* graph = (const float*)d_in[1];
    const float* W1    = (const float*)d_in[2];
    const float* b1    = (const float*)d_in[3];
    const float* W2    = (const float*)d_in[4];
    const float* b2    = (const float*)d_in[5];
    float* out = (float*)d_out;

    constexpr int SM1 = (3 * 4096 + 3 * 32 * 72) * 4;   // 76800 B
    constexpr int SM2 = (3 * 4096 + 3 * 32 * 40) * 4;   // 64512 B
    cudaFuncSetAttribute(k_prop<HC, 72, true>,
                         cudaFuncAttributeMaxDynamicSharedMemorySize, SM1);
    cudaFuncSetAttribute(k_prop<OC, 40, false>,
                         cudaFuncAttributeMaxDynamicSharedMemorySize, SM2);

    k_lin1<<<BB * NN / 64, 256>>>(x, W1, b1);
    k_prop<HC, 72, true><<<BB * 8, 256, SM1>>>(graph, nullptr);
    k_lin2<<<BB * NN / 64, 256>>>(W2, b2);
    k_prop<OC, 40, false><<<BB * 8, 256, SM2>>>(graph, out);
}